// round 14
// baseline (speedup 1.0000x reference)
#include <cuda_runtime.h>
#include <math.h>

#define EPSF 1e-8f
#define BATCH 16
#define NBLK3 144   // 16 sinkhorn + 128 dmloss blocks in k_back

// ---------------- scratch (device globals; no allocation allowed) ----------------
__device__ float g_cvh[2][BATCH][128 * 128];   // horizontal gaussian pass
__device__ float g_cvv[2][BATCH][128 * 128];   // vertical gaussian pass (smoothed)
__device__ float g_ot8[2][BATCH][64 * 64];     // block-8 sums
__device__ float g_spart[2][BATCH][16];        // per-rowchunk partial sums of density
__device__ float g_sums[2][BATCH];             // per-batch totals (written by sinkhorn)
__device__ float g_vpart[2][BATCH][4];         // per-chunk sums of smoothed field
__device__ float g_dmpart[BATCH][8];           // per-chunk kl+l2 partials
__device__ float g_ot_pb[BATCH];               // per-batch masked OT cost
__device__ unsigned g_ctr = 0;                 // arrival counter for k_back (self-resetting)

// ---------------- helpers ----------------
__device__ __forceinline__ float block_reduce(float v, float* scratch)
{
    int tid = threadIdx.x + threadIdx.y * blockDim.x;
    unsigned m = 0xffffffffu;
#pragma unroll
    for (int o = 16; o > 0; o >>= 1) v += __shfl_down_sync(m, v, o);
    int lane = tid & 31, w = tid >> 5;
    int nw = (blockDim.x * blockDim.y + 31) >> 5;
    if (lane == 0) scratch[w] = v;
    __syncthreads();
    v = (tid < nw) ? scratch[tid] : 0.f;
    __syncthreads();
    if (w == 0) {
#pragma unroll
        for (int o = 16; o > 0; o >>= 1) v += __shfl_down_sync(m, v, o);
    }
    return v;  // valid in thread 0
}

__device__ __forceinline__ void make_gauss(float* gk, float* ginv, int tid)
{
    if (tid < 49) {
        float d = (float)tid - 24.f;
        gk[tid] = expf(-(d * d) * (1.f / 128.f));
    }
    __syncthreads();
    if (tid == 0) {
        float s = 0.f;
        for (int i = 0; i < 49; ++i) s += gk[i];
        *ginv = 1.f / s;
    }
    __syncthreads();
}

// ==== K1: 4x4 block sums + fused horizontal gaussian + ot8 cells + partial sums ====
// Block = dm4 rows [8*ych, 8*ych+8) x all 128 cols; 512 threads (2 cells / 2 conv outs each).
__global__ void __launch_bounds__(512) k_front(const float* __restrict__ pred,
                                               const float* __restrict__ gt)
{
    __shared__ float sdm[8][176];   // cols [24,152) = dm4 data, rest zero
    __shared__ float gk[49];
    __shared__ float ginv;
    __shared__ float red[32];
    int ych = blockIdx.x;           // 0..15
    int img = blockIdx.y;
    int arr = img >> 4, b = img & 15;
    const float* in = (arr ? gt : pred) + (size_t)b * 512 * 512;
    int tid = threadIdx.x;

    for (int i = tid; i < 8 * 176; i += 512) (&sdm[0][0])[i] = 0.f;
    make_gauss(gk, &ginv, tid);     // syncs inside also publish the zeroed smem

    // 4x4 block sums into smem (+ per-thread partial for spart): 2 cells/thread
    float psum = 0.f;
    for (int i = tid; i < 1024; i += 512) {
        int r = i >> 7, c = i & 127;
        float s = 0.f;
#pragma unroll
        for (int rr = 0; rr < 4; ++rr) {
            float4 v = *reinterpret_cast<const float4*>(
                in + (size_t)(ych * 32 + 4 * r + rr) * 512 + 4 * c);
            s += v.x + v.y + v.z + v.w;
        }
        sdm[r][c + 24] = s;
        psum += s;
    }
    __syncthreads();

    // 8x8 ot cells (2x2 of dm4) for this 8-row band
    if (tid < 256) {
        int rr = tid >> 6, cc = tid & 63;   // 4 rows x 64 cols = 256 cells
        float v = sdm[2 * rr][2 * cc + 24] + sdm[2 * rr][2 * cc + 25] +
                  sdm[2 * rr + 1][2 * cc + 24] + sdm[2 * rr + 1][2 * cc + 25];
        g_ot8[arr][b][(ych * 4 + rr) * 64 + cc] = v;
    }

    // per-band density partial sum (block_reduce contains syncs; sdm untouched after)
    float tot = block_reduce(psum, red);
    if (tid == 0) g_spart[arr][b][ych] = tot;

    // horizontal 49-tap conv: thread = (row, x), 2 outputs strided by 64 (stride-1 LDS)
    int r = tid >> 6, tx = tid & 63;
    float acc0 = 0.f, acc1 = 0.f;
#pragma unroll
    for (int j = 0; j < 49; ++j) {
        float wj = gk[j];
        acc0 = fmaf(wj, sdm[r][tx + j], acc0);
        acc1 = fmaf(wj, sdm[r][tx + 64 + j], acc1);
    }
    float gi = ginv;
    float* op = g_cvh[arr][b] + (ych * 8 + r) * 128 + tx;
    op[0] = acc0 * gi;
    op[64] = acc1 * gi;
}

// ==== K2: vertical 49-tap gaussian, 16 outputs/thread, register window + partial sums ====
__global__ void __launch_bounds__(256) k_convv()
{
    __shared__ float s[80 * 128];
    __shared__ float gk[49];
    __shared__ float ginv;
    __shared__ float red[32];
    int img = blockIdx.y;
    int arr = img >> 4, bb = img & 15;
    int ybase = blockIdx.x * 32;
    int tid = threadIdx.x;  // 256
    const float* in = g_cvh[arr][bb];
    float* out = g_cvv[arr][bb];
    make_gauss(gk, &ginv, tid);
    for (int i = tid; i < 80 * 128; i += 256) {
        int r = i >> 7, x = i & 127;
        int sy = ybase - 24 + r;
        s[i] = (sy >= 0 && sy < 128) ? in[sy * 128 + x] : 0.f;
    }
    __syncthreads();
    int x = tid & 127;
    int yo = (tid >> 7) * 16;  // 0 or 16: local output base
    const float* col0 = &s[yo * 128 + x];
    float win[64];
#pragma unroll
    for (int t = 0; t < 64; ++t) win[t] = col0[t * 128];
    float acc[16];
#pragma unroll
    for (int k = 0; k < 16; ++k) acc[k] = 0.f;
#pragma unroll
    for (int j = 0; j < 49; ++j) {
        float wj = gk[j];
#pragma unroll
        for (int k = 0; k < 16; ++k) acc[k] = fmaf(wj, win[j + k], acc[k]);
    }
    float gi = ginv;
    float loc = 0.f;
#pragma unroll
    for (int k = 0; k < 16; ++k) {
        float v = acc[k] * gi;
        out[(ybase + yo + k) * 128 + x] = v;
        loc += v;
    }
    float tot = block_reduce(loc, red);
    if (tid == 0) g_vpart[arr][bb][blockIdx.x] = tot;
}

// ==== K3: sinkhorn (blocks 0-15) + dm KL/L2 (blocks 16-143) + final via last-block ====
// Sinkhorn @512 threads: warp owns 4 rows; interior y-neighbors stay in-register, only
// warp-boundary row-sums hit smem. t = rs + w1*(rs_up + rs_down), rs = f + w1*(f_l + f_r).
__global__ void __launch_bounds__(512) k_back(const int* __restrict__ gt_counts,
                                              const int* __restrict__ cell_area,
                                              float* __restrict__ out)
{
    __shared__ float RSa[66 * 64], RSb[66 * 64];  // buffer row k = field row k-1; halos 0
    __shared__ float Uw[66 * 66];                 // padded final-u field for cost epilogue
    __shared__ float red[32];
    __shared__ float s2[2];
    __shared__ int lastf;
    int bid = blockIdx.x;
    int tid = threadIdx.x;
    int w = tid >> 5, lane = tid & 31;
    unsigned M = 0xffffffffu;
    if (tid == 0) lastf = 0;

    if (bid < 16) {
        // ---------------- Sinkhorn for batch b = bid ----------------
        int b = bid;
        for (int i = tid; i < 66 * 64; i += 512) { RSa[i] = 0.f; RSb[i] = 0.f; }
        for (int i = tid; i < 66 * 66; i += 512) Uw[i] = 0.f;
        if (w < 2) {  // reduce the 16 per-band partials per array
            float v = (lane < 16) ? g_spart[w][b][lane] : 0.f;
#pragma unroll
            for (int o = 16; o > 0; o >>= 1) v += __shfl_down_sync(M, v, o);
            if (lane == 0) s2[w] = v;
        }
        __syncthreads();
        float asum = fmaxf(s2[0], EPSF);
        float bsum = fmaxf(s2[1], EPSF);

        const float w1 = expf(-10.f);
        const float w2 = expf(-20.f);
        int yb = 4 * w;          // warp's first field row
        int x0 = 2 * lane;
        const float* pa = g_ot8[0][b];
        const float* pb = g_ot8[1][b];
        float av[4][2], bv[4][2], uu[4][2], vv[4][2];
#pragma unroll
        for (int r = 0; r < 4; ++r) {
            av[r][0] = pa[(yb + r) * 64 + x0] / asum;
            av[r][1] = pa[(yb + r) * 64 + x0 + 1] / asum;
            bv[r][0] = pb[(yb + r) * 64 + x0] / bsum;
            bv[r][1] = pb[(yb + r) * 64 + x0 + 1] / bsum;
            uu[r][0] = 1.f; uu[r][1] = 1.f;
        }

        float2* A2 = reinterpret_cast<float2*>(RSa);
        float2* B2 = reinterpret_cast<float2*>(RSb);

        for (int it = 0; it < 50; ++it) {
            {   // half A: v = b / (K @ u)
                float2 rs[4];
#pragma unroll
                for (int r = 0; r < 4; ++r) {
                    float fl = __shfl_up_sync(M, uu[r][1], 1);   if (lane == 0)  fl = 0.f;
                    float fr = __shfl_down_sync(M, uu[r][0], 1); if (lane == 31) fr = 0.f;
                    rs[r].x = fmaf(w1, fl + uu[r][1], uu[r][0]);
                    rs[r].y = fmaf(w1, uu[r][0] + fr, uu[r][1]);
                }
                A2[(yb + 1) * 32 + lane] = rs[0];   // field row yb   -> buf row yb+1
                A2[(yb + 4) * 32 + lane] = rs[3];   // field row yb+3 -> buf row yb+4
                __syncthreads();
                float2 top = A2[yb * 32 + lane];        // field row yb-1
                float2 bot = A2[(yb + 5) * 32 + lane];  // field row yb+4
                float2 t0, t1, t2, t3;
                t0.x = fmaf(w1, top.x + rs[1].x, rs[0].x);
                t0.y = fmaf(w1, top.y + rs[1].y, rs[0].y);
                t1.x = fmaf(w1, rs[0].x + rs[2].x, rs[1].x);
                t1.y = fmaf(w1, rs[0].y + rs[2].y, rs[1].y);
                t2.x = fmaf(w1, rs[1].x + rs[3].x, rs[2].x);
                t2.y = fmaf(w1, rs[1].y + rs[3].y, rs[2].y);
                t3.x = fmaf(w1, rs[2].x + bot.x, rs[3].x);
                t3.y = fmaf(w1, rs[2].y + bot.y, rs[3].y);
                vv[0][0] = __fdividef(bv[0][0], t0.x + EPSF);
                vv[0][1] = __fdividef(bv[0][1], t0.y + EPSF);
                vv[1][0] = __fdividef(bv[1][0], t1.x + EPSF);
                vv[1][1] = __fdividef(bv[1][1], t1.y + EPSF);
                vv[2][0] = __fdividef(bv[2][0], t2.x + EPSF);
                vv[2][1] = __fdividef(bv[2][1], t2.y + EPSF);
                vv[3][0] = __fdividef(bv[3][0], t3.x + EPSF);
                vv[3][1] = __fdividef(bv[3][1], t3.y + EPSF);
            }
            {   // half B: u = a / (K @ v)
                float2 rs[4];
#pragma unroll
                for (int r = 0; r < 4; ++r) {
                    float fl = __shfl_up_sync(M, vv[r][1], 1);   if (lane == 0)  fl = 0.f;
                    float fr = __shfl_down_sync(M, vv[r][0], 1); if (lane == 31) fr = 0.f;
                    rs[r].x = fmaf(w1, fl + vv[r][1], vv[r][0]);
                    rs[r].y = fmaf(w1, vv[r][0] + fr, vv[r][1]);
                }
                B2[(yb + 1) * 32 + lane] = rs[0];
                B2[(yb + 4) * 32 + lane] = rs[3];
                __syncthreads();
                float2 top = B2[yb * 32 + lane];
                float2 bot = B2[(yb + 5) * 32 + lane];
                float2 t0, t1, t2, t3;
                t0.x = fmaf(w1, top.x + rs[1].x, rs[0].x);
                t0.y = fmaf(w1, top.y + rs[1].y, rs[0].y);
                t1.x = fmaf(w1, rs[0].x + rs[2].x, rs[1].x);
                t1.y = fmaf(w1, rs[0].y + rs[2].y, rs[1].y);
                t2.x = fmaf(w1, rs[1].x + rs[3].x, rs[2].x);
                t2.y = fmaf(w1, rs[1].y + rs[3].y, rs[2].y);
                t3.x = fmaf(w1, rs[2].x + bot.x, rs[3].x);
                t3.y = fmaf(w1, rs[2].y + bot.y, rs[3].y);
                uu[0][0] = __fdividef(av[0][0], t0.x + EPSF);
                uu[0][1] = __fdividef(av[0][1], t0.y + EPSF);
                uu[1][0] = __fdividef(av[1][0], t1.x + EPSF);
                uu[1][1] = __fdividef(av[1][1], t1.y + EPSF);
                uu[2][0] = __fdividef(av[2][0], t2.x + EPSF);
                uu[2][1] = __fdividef(av[2][1], t2.y + EPSF);
                uu[3][0] = __fdividef(av[3][0], t3.x + EPSF);
                uu[3][1] = __fdividef(av[3][1], t3.y + EPSF);
            }
        }

        // cost epilogue: sum_j v_j * (w1*S1(u) + 2*w2*S2(u)); diagonal C=0
#pragma unroll
        for (int r = 0; r < 4; ++r) {
            float* Ur = Uw + (yb + r + 1) * 66 + (x0 + 1);
            Ur[0] = uu[r][0];
            Ur[1] = uu[r][1];
        }
        __syncthreads();
        float tw2 = 2.f * w2;
        float c = 0.f;
#pragma unroll
        for (int r = 0; r < 4; ++r) {
#pragma unroll
            for (int cc = 0; cc < 2; ++cc) {
                const float* p = Uw + (yb + r + 1) * 66 + (x0 + cc + 1);
                float s1v = p[-66] + p[66] + p[-1] + p[1];
                float s2v = p[-67] + p[-65] + p[65] + p[67];
                c += vv[r][cc] * fmaf(w1, s1v, tw2 * s2v);
            }
        }
        float tot = block_reduce(c, red);
        if (tid == 0) {
            g_sums[0][b] = asum;
            g_sums[1][b] = bsum;
            bool mask = (asum > 0.5f) && (bsum > 0.5f);
            g_ot_pb[b] = mask ? tot : 0.f;
        }
    } else {
        // ---------------- DM KL + L2 chunk (float4: 512 x 4 = 2048 elems) ----------------
        int idx = bid - 16;
        int b = idx >> 3, chunk = idx & 7;
        float sp = g_vpart[0][b][0] + g_vpart[0][b][1] + g_vpart[0][b][2] + g_vpart[0][b][3];
        float sg = g_vpart[1][b][0] + g_vpart[1][b][1] + g_vpart[1][b][2] + g_vpart[1][b][3];
        float ip = 1.f / fmaxf(sp, EPSF);
        float ig = 1.f / fmaxf(sg, EPSF);
        const float4* ps = reinterpret_cast<const float4*>(g_cvv[0][b] + chunk * 2048);
        const float4* gs = reinterpret_cast<const float4*>(g_cvv[1][b] + chunk * 2048);
        float4 pv = ps[tid];
        float4 gv = gs[tid];
        float acc = 0.f;
#pragma unroll
        for (int k = 0; k < 4; ++k) {
            float pn = (&pv.x)[k] * ip, gn = (&gv.x)[k] * ig;
            float kl = gn * __logf(__fdividef(gn + EPSF, pn + EPSF));
            float d = pn - gn;
            acc += kl + d * d;
        }
        float tot = block_reduce(acc, red);
        if (tid == 0) g_dmpart[b][chunk] = tot;
    }

    // ---------------- last-block final (deterministic: fenced partials, single writer) ----
    if (tid == 0) {
        __threadfence();
        if (atomicAdd(&g_ctr, 1u) == (unsigned)(NBLK3 - 1)) lastf = 1;
    }
    __syncthreads();
    if (lastf && w == 0) {
        __threadfence();  // acquire: order reads after the counter observation
        if (lane == 0) g_ctr = 0;  // self-reset for next launch/replay
        float cl = 0.f, dm = 0.f, ot = 0.f;
        if (lane < BATCH) {
            int craw = cell_area[0];
            // robust to int32 or float32 encoding of the scalar (both yield 1.0 here)
            float ca = (craw >= 1 && craw <= 1000000) ? (float)craw : __int_as_float(craw);
            float pc = fmaxf(g_sums[0][lane] / ca, 0.f);
            float d = fabsf(pc - (float)gt_counts[lane]);
            cl = (d < 10.f) ? (0.5f * d * d / 10.f) : (d - 5.f);
#pragma unroll
            for (int c = 0; c < 8; ++c) dm += g_dmpart[lane][c];
            ot = g_ot_pb[lane];
        }
#pragma unroll
        for (int o = 16; o > 0; o >>= 1) {
            cl += __shfl_down_sync(M, cl, o);
            dm += __shfl_down_sync(M, dm, o);
            ot += __shfl_down_sync(M, ot, o);
        }
        if (lane == 0) {
            out[0] = 3.0f * (cl * (1.f / 16.f)) + 0.5f * (dm * (1.f / 16.f)) +
                     0.3f * (ot * (1.f / 16.f));
        }
    }
}

// ---------------- launch ----------------
extern "C" void kernel_launch(void* const* d_in, const int* in_sizes, int n_in,
                              void* d_out, int out_size)
{
    const float* pred = (const float*)d_in[0];
    const float* gt = (const float*)d_in[1];
    const int* counts = (const int*)d_in[2];
    const int* cell = (const int*)d_in[3];
    float* out = (float*)d_out;

    k_front<<<dim3(16, 32), 512>>>(pred, gt);
    k_convv<<<dim3(4, 32), 256>>>();
    k_back<<<NBLK3, 512>>>(counts, cell, out);
}